// round 5
// baseline (speedup 1.0000x reference)
#include <cuda_runtime.h>
#include <math.h>
#include <stdint.h>

// Problem shapes (fixed for this bench)
#define BB 4
#define TT 512
#define SS 1024
#define HH 768
#define VV 50257

// Scratch for the collapsed p_gen projections (device globals: no allocation).
__device__ float g_u[BB * SS];   // u[b,s] = src[b,s,:] . W_pgen[:H]
__device__ float g_v[BB * TT];   // v[b,t] = tgt[b,t,:] . W_pgen[H:] + bias

// ---------------------------------------------------------------------------
// Kernel 1: tiny projections. One warp per row (B*S + B*T = 6144 rows).
// ---------------------------------------------------------------------------
__global__ void pgen_prep_kernel(const float* __restrict__ src,
                                 const float* __restrict__ tgt,
                                 const float* __restrict__ W,
                                 const float* __restrict__ bias)
{
    const int warp = (blockIdx.x * blockDim.x + threadIdx.x) >> 5;
    const int lane = threadIdx.x & 31;
    const int NU = BB * SS;
    const int NV = BB * TT;

    if (warp < NU) {
        const float4* x = reinterpret_cast<const float4*>(src + (size_t)warp * HH);
        const float4* w = reinterpret_cast<const float4*>(W);
        float acc = 0.f;
        #pragma unroll
        for (int j = lane; j < HH / 4; j += 32) {
            float4 a = x[j], b = w[j];
            acc += a.x * b.x + a.y * b.y + a.z * b.z + a.w * b.w;
        }
        #pragma unroll
        for (int o = 16; o; o >>= 1) acc += __shfl_xor_sync(0xffffffffu, acc, o);
        if (lane == 0) g_u[warp] = acc;
    } else if (warp < NU + NV) {
        const int r = warp - NU;
        const float4* x = reinterpret_cast<const float4*>(tgt + (size_t)r * HH);
        const float4* w = reinterpret_cast<const float4*>(W + HH);
        float acc = 0.f;
        #pragma unroll
        for (int j = lane; j < HH / 4; j += 32) {
            float4 a = x[j], b = w[j];
            acc += a.x * b.x + a.y * b.y + a.z * b.z + a.w * b.w;
        }
        #pragma unroll
        for (int o = 16; o; o >>= 1) acc += __shfl_xor_sync(0xffffffffu, acc, o);
        if (lane == 0) g_v[r] = acc + bias[0];
    }
}

// ---------------------------------------------------------------------------
// Kernel 2: one CTA per (b,t) row. NO vocab accumulator in shared memory:
//   phase 1: stream zeros for the whole row straight to GMEM (STG.128)
//   phase 2: 1024 scattered global atomicAdds (REDG) for the nonzeros
// Each output byte touches L1 exactly once. p_gen reduction fused (uses the
// attn value already in registers).
// ---------------------------------------------------------------------------
__global__ __launch_bounds__(1024, 2)
void copy_logits_kernel(const int* __restrict__ ids,
                        const float* __restrict__ attn,
                        float* __restrict__ out_pgen,
                        float* __restrict__ out_logits)
{
    __shared__ float red[32];
    const int row = blockIdx.x;            // b*T + t
    const int b   = row / TT;
    const int tid = threadIdx.x;

    // Kick off phase-2 input loads early (independent of the zero-fill).
    const float a  = attn[(size_t)row * SS + tid];
    const int   id = ids[b * SS + tid];
    const float u  = g_u[b * SS + tid];

    // Phase 1: zero the entire row in GMEM with vectorized streaming stores.
    // Row base offset cycles mod 16B (stride 50257*4), so peel head/tail.
    float* dst = out_logits + (size_t)row * VV;
    const int head = (int)(((16u - ((uint32_t)(uintptr_t)dst & 15u)) & 15u) >> 2);

    if (tid < head) __stcs(dst + tid, 0.f);

    const int nvec = (VV - head) >> 2;                 // full float4 stores
    float4* dst4 = reinterpret_cast<float4*>(dst + head);
    const float4 z4 = make_float4(0.f, 0.f, 0.f, 0.f);
    #pragma unroll 4
    for (int i = tid; i < nvec; i += 1024) __stcs(dst4 + i, z4);

    const int tail = head + 4 * nvec;
    if (tid < VV - tail) __stcs(dst + tail + tid, 0.f);

    // Block-wide: zeros visible to subsequent atomics from this block.
    __syncthreads();

    // Phase 2: scattered accumulation (compiles to RED.ADD.F32, no return).
    atomicAdd(dst + id, a);

    // Fused p_gen = sigmoid(attn . u + v).
    float part = a * u;
    #pragma unroll
    for (int o = 16; o; o >>= 1) part += __shfl_xor_sync(0xffffffffu, part, o);
    if ((tid & 31) == 0) red[tid >> 5] = part;
    __syncthreads();
    if (tid < 32) {
        float x = red[tid];
        #pragma unroll
        for (int o = 16; o; o >>= 1) x += __shfl_xor_sync(0xffffffffu, x, o);
        if (tid == 0) {
            const float zv = x + g_v[row];
            out_pgen[row] = 1.f / (1.f + __expf(-zv));
        }
    }
}

// ---------------------------------------------------------------------------
// Launch
// ---------------------------------------------------------------------------
extern "C" void kernel_launch(void* const* d_in, const int* in_sizes, int n_in,
                              void* d_out, int out_size)
{
    const int*   ids  = (const int*)  d_in[0];  // [B,S] int32
    const float* attn = (const float*)d_in[1];  // [B,T,S]
    const float* src  = (const float*)d_in[2];  // [B,S,H]
    const float* tgt  = (const float*)d_in[3];  // [B,T,H]
    const float* W    = (const float*)d_in[4];  // [2H,1]
    const float* bias = (const float*)d_in[5];  // [1]

    float* out_pgen   = (float*)d_out;              // [B,T]  (first output)
    float* out_logits = out_pgen + (size_t)BB * TT; // [B,T,V]

    pgen_prep_kernel<<<(BB * SS + BB * TT) / 8, 256>>>(src, tgt, W, bias);

    copy_logits_kernel<<<BB * TT, 1024>>>(ids, attn, out_pgen, out_logits);
}

// round 6
// speedup vs baseline: 1.5189x; 1.5189x over previous
#include <cuda_runtime.h>
#include <math.h>
#include <stdint.h>

// Problem shapes (fixed for this bench)
#define BB 4
#define TT 512
#define SS 1024
#define HH 768
#define VV 50257

// Vocab split: two CTAs per (b,t) row.
#define VLO1   25129                 // half0 = [0,25129), half1 = [25129,50257)
#define VPADH  25136                 // accumulator floats (pad<=3 + n<=25129, rounded up)
#define SMEM_FLOATS (VPADH + 32)
#define SMEM_BYTES  (SMEM_FLOATS * 4)

// Scratch for the collapsed p_gen projections (device globals: no allocation).
__device__ float g_u[BB * SS];   // u[b,s] = src[b,s,:] . W_pgen[:H]
__device__ float g_v[BB * TT];   // v[b,t] = tgt[b,t,:] . W_pgen[H:] + bias

// ---------------------------------------------------------------------------
// Kernel 1: tiny projections. One warp per row (B*S + B*T = 6144 rows).
// ---------------------------------------------------------------------------
__global__ void pgen_prep_kernel(const float* __restrict__ src,
                                 const float* __restrict__ tgt,
                                 const float* __restrict__ W,
                                 const float* __restrict__ bias)
{
    const int warp = (blockIdx.x * blockDim.x + threadIdx.x) >> 5;
    const int lane = threadIdx.x & 31;
    const int NU = BB * SS;
    const int NV = BB * TT;

    if (warp < NU) {
        const float4* x = reinterpret_cast<const float4*>(src + (size_t)warp * HH);
        const float4* w = reinterpret_cast<const float4*>(W);
        float acc = 0.f;
        #pragma unroll
        for (int j = lane; j < HH / 4; j += 32) {
            float4 a = x[j], b = w[j];
            acc += a.x * b.x + a.y * b.y + a.z * b.z + a.w * b.w;
        }
        #pragma unroll
        for (int o = 16; o; o >>= 1) acc += __shfl_xor_sync(0xffffffffu, acc, o);
        if (lane == 0) g_u[warp] = acc;
    } else if (warp < NU + NV) {
        const int r = warp - NU;
        const float4* x = reinterpret_cast<const float4*>(tgt + (size_t)r * HH);
        const float4* w = reinterpret_cast<const float4*>(W + HH);
        float acc = 0.f;
        #pragma unroll
        for (int j = lane; j < HH / 4; j += 32) {
            float4 a = x[j], b = w[j];
            acc += a.x * b.x + a.y * b.y + a.z * b.z + a.w * b.w;
        }
        #pragma unroll
        for (int o = 16; o; o >>= 1) acc += __shfl_xor_sync(0xffffffffu, acc, o);
        if (lane == 0) g_v[r] = acc + bias[0];
    }
}

// ---------------------------------------------------------------------------
// Kernel 2: two CTAs per (b,t) row, each owning half the vocab.
//   Phase 1: zero ~100KB smem accumulator (STS.128)
//   Phase 2: range-predicated shared atomicAdd scatter (+ fused p_gen, half 0)
//   Phase 3: ONE bulk-async (TMA) copy smem -> gmem for the half-row.
// The TMA engine reads smem and writes L2/DRAM directly: no LDS readback, no
// per-element STG, L1/LSU path nearly idle during the drain. 2 CTAs/SM so one
// CTA's zero/scatter overlaps the other's DRAM-bound TMA drain.
// ---------------------------------------------------------------------------
__global__ __launch_bounds__(1024, 2)
void copy_logits_kernel(const int* __restrict__ ids,
                        const float* __restrict__ attn,
                        float* __restrict__ out_pgen,
                        float* __restrict__ out_logits)
{
    extern __shared__ float sm[];          // [VPADH] accumulator + [32] reduce
    const int row  = blockIdx.x >> 1;      // b*T + t
    const int half = blockIdx.x & 1;
    const int b    = row / TT;
    const int tid  = threadIdx.x;

    const int lo = half ? VLO1 : 0;
    const int hi = half ? VV   : VLO1;
    const int n  = hi - lo;

    // Global destination of this half-row; its 16B phase decides head & pad.
    float* dst = out_logits + (size_t)row * VV + lo;
    const int head = (int)(((16u - ((uint32_t)(uintptr_t)dst & 15u)) & 15u) >> 2); // 0..3
    const int pad  = (4 - head) & 3;       // smem offset so sm[pad+head] is 16B-aligned

    // Phase 1: zero the accumulator (vectorized STS.128).
    float4* sm4 = reinterpret_cast<float4*>(sm);
    const float4 z4 = make_float4(0.f, 0.f, 0.f, 0.f);
    #pragma unroll
    for (int i = tid; i < VPADH / 4; i += 1024) sm4[i] = z4;
    __syncthreads();

    // Phase 2: range-predicated scatter-add. Exactly S=1024 threads, 1 each.
    const float a  = attn[(size_t)row * SS + tid];
    const int   id = ids[b * SS + tid];
    if (id >= lo && id < hi) atomicAdd(&sm[pad + id - lo], a);

    if (half == 0) {
        // Fused p_gen = sigmoid(attn . u + v) using the attn value in hand.
        float part = a * g_u[b * SS + tid];
        #pragma unroll
        for (int o = 16; o; o >>= 1) part += __shfl_xor_sync(0xffffffffu, part, o);
        float* red = sm + VPADH;
        if ((tid & 31) == 0) red[tid >> 5] = part;
        __syncthreads();   // atomics + warp partials complete
        if (tid < 32) {
            float x = red[tid];
            #pragma unroll
            for (int o = 16; o; o >>= 1) x += __shfl_xor_sync(0xffffffffu, x, o);
            if (tid == 0) {
                const float zv = x + g_v[row];
                out_pgen[row] = 1.f / (1.f + __expf(-zv));
            }
        }
    } else {
        __syncthreads();   // atomics complete
    }

    // Phase 3: head/tail scalars + one bulk-async copy for the aligned middle.
    const int nvec = (n - head) >> 2;          // 16B chunks in the middle
    const int tail = head + 4 * nvec;

    if (tid < head)        __stcs(dst + tid, sm[pad + tid]);
    if (tid < n - tail)    __stcs(dst + tail + tid, sm[pad + tail + tid]);

    if (tid == 0) {
        // Order generic-proxy smem writes (STS/ATOMS) before async-proxy read.
        asm volatile("fence.proxy.async.shared::cta;" ::: "memory");
        uint32_t saddr;
        asm("{ .reg .u64 t; cvta.to.shared.u64 t, %1; cvt.u32.u64 %0, t; }"
            : "=r"(saddr) : "l"(sm + pad + head));
        asm volatile(
            "cp.async.bulk.global.shared::cta.bulk_group [%0], [%1], %2;"
            :: "l"(dst + head), "r"(saddr), "r"(16 * nvec) : "memory");
        asm volatile("cp.async.bulk.commit_group;" ::: "memory");
        asm volatile("cp.async.bulk.wait_group 0;" ::: "memory");
    }
}

// ---------------------------------------------------------------------------
// Launch
// ---------------------------------------------------------------------------
extern "C" void kernel_launch(void* const* d_in, const int* in_sizes, int n_in,
                              void* d_out, int out_size)
{
    const int*   ids  = (const int*)  d_in[0];  // [B,S] int32
    const float* attn = (const float*)d_in[1];  // [B,T,S]
    const float* src  = (const float*)d_in[2];  // [B,S,H]
    const float* tgt  = (const float*)d_in[3];  // [B,T,H]
    const float* W    = (const float*)d_in[4];  // [2H,1]
    const float* bias = (const float*)d_in[5];  // [1]

    float* out_pgen   = (float*)d_out;              // [B,T]  (first output)
    float* out_logits = out_pgen + (size_t)BB * TT; // [B,T,V]

    cudaFuncSetAttribute(copy_logits_kernel,
                         cudaFuncAttributeMaxDynamicSharedMemorySize,
                         SMEM_BYTES);

    pgen_prep_kernel<<<(BB * SS + BB * TT) / 8, 256>>>(src, tgt, W, bias);

    copy_logits_kernel<<<BB * TT * 2, 1024, SMEM_BYTES>>>(ids, attn, out_pgen,
                                                          out_logits);
}

// round 7
// speedup vs baseline: 1.5292x; 1.0067x over previous
#include <cuda_runtime.h>
#include <math.h>
#include <stdint.h>

// Problem shapes (fixed for this bench)
#define BB 4
#define TT 512
#define SS 1024
#define HH 768
#define VV 50257

// Vocab split: two CTAs per (b,t) row.
#define VLO1   25129                 // half0 = [0,25129), half1 = [25129,50257)
#define VPADH  25136                 // accumulator floats (pad<=3 + n<=25129, rounded)
#define SMEM_FLOATS (VPADH + 32)
#define SMEM_BYTES  (SMEM_FLOATS * 4)

// Scratch for the collapsed p_gen projections (device globals: no allocation).
__device__ float g_u[BB * SS];   // u[b,s] = src[b,s,:] . W_pgen[:H]
__device__ float g_v[BB * TT];   // v[b,t] = tgt[b,t,:] . W_pgen[H:] + bias

// ---------------------------------------------------------------------------
// Kernel 1: tiny projections. One warp per row (B*S + B*T = 6144 rows).
// Triggers programmatic launch completion immediately so the copy kernel can
// begin its g_u-independent phases concurrently.
// ---------------------------------------------------------------------------
__global__ void pgen_prep_kernel(const float* __restrict__ src,
                                 const float* __restrict__ tgt,
                                 const float* __restrict__ W,
                                 const float* __restrict__ bias)
{
#if __CUDA_ARCH__ >= 900
    cudaTriggerProgrammaticLaunchCompletion();
#endif
    const int warp = (blockIdx.x * blockDim.x + threadIdx.x) >> 5;
    const int lane = threadIdx.x & 31;
    const int NU = BB * SS;
    const int NV = BB * TT;

    if (warp < NU) {
        const float4* x = reinterpret_cast<const float4*>(src + (size_t)warp * HH);
        const float4* w = reinterpret_cast<const float4*>(W);
        float acc = 0.f;
        #pragma unroll
        for (int j = lane; j < HH / 4; j += 32) {
            float4 a = x[j], b = w[j];
            acc += a.x * b.x + a.y * b.y + a.z * b.z + a.w * b.w;
        }
        #pragma unroll
        for (int o = 16; o; o >>= 1) acc += __shfl_xor_sync(0xffffffffu, acc, o);
        if (lane == 0) g_u[warp] = acc;
    } else if (warp < NU + NV) {
        const int r = warp - NU;
        const float4* x = reinterpret_cast<const float4*>(tgt + (size_t)r * HH);
        const float4* w = reinterpret_cast<const float4*>(W + HH);
        float acc = 0.f;
        #pragma unroll
        for (int j = lane; j < HH / 4; j += 32) {
            float4 a = x[j], b = w[j];
            acc += a.x * b.x + a.y * b.y + a.z * b.z + a.w * b.w;
        }
        #pragma unroll
        for (int o = 16; o; o >>= 1) acc += __shfl_xor_sync(0xffffffffu, acc, o);
        if (lane == 0) g_v[r] = acc + bias[0];
    }
}

// ---------------------------------------------------------------------------
// Kernel 2: two CTAs per (b,t) row, each owning half the vocab.
//   Phase 1: zero ~100KB smem accumulator (STS.128)
//   Phase 2: range-predicated shared atomicAdd scatter
//   Phase 3: ONE bulk-async (TMA) copy smem -> gmem for the half-row
//   Phase 4 (half 0 only): grid-dep sync on prep, fused p_gen reduction —
//            overlapped with this CTA's own TMA drain.
// ---------------------------------------------------------------------------
__global__ __launch_bounds__(1024, 2)
void copy_logits_kernel(const int* __restrict__ ids,
                        const float* __restrict__ attn,
                        float* __restrict__ out_pgen,
                        float* __restrict__ out_logits)
{
    extern __shared__ float sm[];          // [VPADH] accumulator + [32] reduce
    const int row  = blockIdx.x >> 1;      // b*T + t
    const int half = blockIdx.x & 1;
    const int b    = row / TT;
    const int tid  = threadIdx.x;

    const int lo = half ? VLO1 : 0;
    const int hi = half ? VV   : VLO1;
    const int n  = hi - lo;

    // Global destination of this half-row; its 16B phase decides head & pad.
    float* dst = out_logits + (size_t)row * VV + lo;
    const int head = (int)(((16u - ((uint32_t)(uintptr_t)dst & 15u)) & 15u) >> 2); // 0..3
    const int pad  = (4 - head) & 3;       // sm[pad+head] is 16B-aligned

    // Phase 1: zero the accumulator (vectorized STS.128).
    float4* sm4 = reinterpret_cast<float4*>(sm);
    const float4 z4 = make_float4(0.f, 0.f, 0.f, 0.f);
    #pragma unroll
    for (int i = tid; i < VPADH / 4; i += 1024) sm4[i] = z4;
    __syncthreads();

    // Phase 2: range-predicated scatter-add. Exactly S=1024 threads, 1 each.
    const float a  = attn[(size_t)row * SS + tid];
    const int   id = ids[b * SS + tid];
    if (id >= lo && id < hi) atomicAdd(&sm[pad + id - lo], a);
    __syncthreads();   // all atomics complete

    // Phase 3: head/tail scalars + one bulk-async copy for the aligned middle.
    const int nvec = (n - head) >> 2;          // 16B chunks in the middle
    const int tail = head + 4 * nvec;

    if (tid < head)     __stcs(dst + tid, sm[pad + tid]);
    if (tid < n - tail) __stcs(dst + tail + tid, sm[pad + tail + tid]);

    if (tid == 0) {
        // Order generic-proxy smem writes (STS/ATOMS) before async-proxy read.
        asm volatile("fence.proxy.async.shared::cta;" ::: "memory");
        uint32_t saddr;
        asm("{ .reg .u64 t; cvta.to.shared.u64 t, %1; cvt.u32.u64 %0, t; }"
            : "=r"(saddr) : "l"(sm + pad + head));
        asm volatile(
            "cp.async.bulk.global.shared::cta.bulk_group [%0], [%1], %2;"
            :: "l"(dst + head), "r"(saddr), "r"(16 * nvec) : "memory");
        asm volatile("cp.async.bulk.commit_group;" ::: "memory");
    }

    // Phase 4: fused p_gen = sigmoid(attn . u + v), half-0 CTAs only.
    // Runs while this CTA's TMA drain is in flight. Requires prep complete.
    if (half == 0) {
#if __CUDA_ARCH__ >= 900
        cudaGridDependencySynchronize();
#endif
        float part = a * g_u[b * SS + tid];
        #pragma unroll
        for (int o = 16; o; o >>= 1) part += __shfl_xor_sync(0xffffffffu, part, o);
        float* red = sm + VPADH;
        if ((tid & 31) == 0) red[tid >> 5] = part;
        __syncthreads();
        if (tid < 32) {
            float x = red[tid];
            #pragma unroll
            for (int o = 16; o; o >>= 1) x += __shfl_xor_sync(0xffffffffu, x, o);
            if (tid == 0) {
                const float zv = x + g_v[row];
                out_pgen[row] = 1.f / (1.f + __expf(-zv));
            }
        }
    }

    if (tid == 0)
        asm volatile("cp.async.bulk.wait_group 0;" ::: "memory");
}

// ---------------------------------------------------------------------------
// Launch: prep, then copy with Programmatic Dependent Launch so copy's
// g_u-independent phases overlap prep. Fallback to plain launch on error.
// ---------------------------------------------------------------------------
extern "C" void kernel_launch(void* const* d_in, const int* in_sizes, int n_in,
                              void* d_out, int out_size)
{
    const int*   ids  = (const int*)  d_in[0];  // [B,S] int32
    const float* attn = (const float*)d_in[1];  // [B,T,S]
    const float* src  = (const float*)d_in[2];  // [B,S,H]
    const float* tgt  = (const float*)d_in[3];  // [B,T,H]
    const float* W    = (const float*)d_in[4];  // [2H,1]
    const float* bias = (const float*)d_in[5];  // [1]

    float* out_pgen   = (float*)d_out;              // [B,T]  (first output)
    float* out_logits = out_pgen + (size_t)BB * TT; // [B,T,V]

    cudaFuncSetAttribute(copy_logits_kernel,
                         cudaFuncAttributeMaxDynamicSharedMemorySize,
                         SMEM_BYTES);

    pgen_prep_kernel<<<(BB * SS + BB * TT) / 8, 256>>>(src, tgt, W, bias);

    // Copy kernel with PDL (programmatic stream serialization).
    cudaLaunchConfig_t cfg = {};
    cfg.gridDim         = dim3(BB * TT * 2, 1, 1);
    cfg.blockDim        = dim3(1024, 1, 1);
    cfg.dynamicSmemBytes = SMEM_BYTES;
    cfg.stream          = 0;
    cudaLaunchAttribute attr[1];
    attr[0].id = cudaLaunchAttributeProgrammaticStreamSerialization;
    attr[0].val.programmaticStreamSerializationAllowed = 1;
    cfg.attrs    = attr;
    cfg.numAttrs = 1;

    cudaError_t e = cudaLaunchKernelEx(&cfg, copy_logits_kernel,
                                       ids, attn, out_pgen, out_logits);
    if (e != cudaSuccess) {
        (void)cudaGetLastError();   // clear; fall back to plain launch
        copy_logits_kernel<<<BB * TT * 2, 1024, SMEM_BYTES>>>(ids, attn,
                                                              out_pgen,
                                                              out_logits);
    }
}